// round 11
// baseline (speedup 1.0000x reference)
#include <cuda_runtime.h>
#include <cuda_fp16.h>
#include <cstdint>

#define NN 100000
#define EMAX 1600000
#define D 64
#define NB 196                 // scan blocks == grid size of csr kernel
#define CSR_THREADS 512

// Scratch (device globals; no allocation allowed)
__device__ __align__(16) __half g_x16[(size_t)NN * D];
__device__ __align__(16) __half g_h16[(size_t)NN * D];
__device__ __align__(16) __half g_agg16[(size_t)NN * D];
__device__ int g_cnt[NN];
__device__ int g_fill[NN];
__device__ int g_row[NN + 1];
__device__ int g_bsum[NB];
__device__ int g_eidx[EMAX];
__device__ int g_is64;
__device__ unsigned g_barcnt[4];   // monotonic ticket barriers (replay-safe)

// ---------------------------------------------------------------------------
// grid barrier: ticket-batched, monotonic across graph replays.
// Each launch contributes exactly gridDim.x arrivals per barrier slot, so
// "my batch" = floor(ticket/G)*G + G is well-defined on every replay.
// Safe: 196 blocks x 512 thr always co-resident on 148 SMs.
// ---------------------------------------------------------------------------
__device__ __forceinline__ void grid_barrier(int slot) {
    __syncthreads();
    if (threadIdx.x == 0) {
        __threadfence();
        unsigned ticket = atomicAdd(&g_barcnt[slot], 1u);
        unsigned goal = (ticket / NB) * NB + NB;
        while (atomicAdd(&g_barcnt[slot], 0u) < goal)
            __nanosleep(64);
    }
    __syncthreads();
}

__device__ __forceinline__ void decode_edge(const int* __restrict__ ei32,
                                            int E, int t, int& s, int& d) {
    if (g_is64) {
        const long long* ei = (const long long*)ei32;
        s = (int)ei[t];
        d = (int)ei[(size_t)E + t];
    } else {
        s = ei32[t];
        d = ei32[(size_t)E + t];
    }
    if ((unsigned)s >= NN) s = 0;
    if ((unsigned)d >= NN) d = 0;
}

// ---------------------------------------------------------------------------
// ONE persistent kernel: zero + cvt16 + dtype probe | count | scan | fill
// ---------------------------------------------------------------------------
__global__ __launch_bounds__(CSR_THREADS)
void csr_build_kernel(const int* __restrict__ ei32, int E,
                      const float* __restrict__ xin) {
    __shared__ int sm[CSR_THREADS];
    int tid = threadIdx.x;
    int gtid = blockIdx.x * CSR_THREADS + tid;
    int gstride = NB * CSR_THREADS;

    // ---- P0a: dtype probe (block 0 only, before anyone needs g_is64) ----
    if (blockIdx.x == 0) {
        int acc = 0;
        for (int t = tid; t < 2048; t += CSR_THREADS) {
            long long w = (long long)t * (2LL * E / 2048) | 1LL;
            acc |= ei32[w];
        }
        sm[tid] = acc;
        __syncthreads();
        for (int off = 256; off > 0; off >>= 1) {
            if (tid < off) sm[tid] |= sm[tid + off];
            __syncthreads();
        }
        if (tid == 0) g_is64 = (sm[0] == 0) ? 1 : 0;
    }
    // ---- P0b: zero counters + fp32->fp16 conversion of x ----
    for (int i = gtid; i < NN; i += gstride) { g_cnt[i] = 0; g_fill[i] = 0; }
    {
        __half2* o = (__half2*)g_x16;
        for (int i = gtid; i < NN * 16; i += gstride) {
            float4 v = ((const float4*)xin)[i];
            o[i * 2 + 0] = __floats2half2_rn(v.x, v.y);
            o[i * 2 + 1] = __floats2half2_rn(v.z, v.w);
        }
    }
    grid_barrier(0);

    // ---- P1: per-dst degree count ----
    for (int t = gtid; t < E; t += gstride) {
        int d;
        if (g_is64) d = (int)((const long long*)ei32)[(size_t)E + t];
        else        d = ei32[(size_t)E + t];
        if ((unsigned)d >= NN) d = 0;
        atomicAdd(&g_cnt[d], 1);
    }
    grid_barrier(1);

    // ---- P2a: per-block sums (block b covers [b*512, b*512+512)) ----
    {
        int i = blockIdx.x * CSR_THREADS + tid;
        sm[tid] = (i < NN) ? g_cnt[i] : 0;
        __syncthreads();
        for (int off = 256; off > 0; off >>= 1) {
            if (tid < off) sm[tid] += sm[tid + off];
            __syncthreads();
        }
        if (tid == 0) g_bsum[blockIdx.x] = sm[0];
    }
    grid_barrier(2);

    // ---- P2b: prefix of bsum + local inclusive scan -> g_row ----
    {
        int pv = (tid < NB && tid < (int)blockIdx.x) ? g_bsum[tid] : 0;
        sm[tid] = pv;
        __syncthreads();
        for (int off = 256; off > 0; off >>= 1) {
            if (tid < off) sm[tid] += sm[tid + off];
            __syncthreads();
        }
        int boff = sm[0];
        __syncthreads();

        int i = blockIdx.x * CSR_THREADS + tid;
        int v = (i < NN) ? g_cnt[i] : 0;
        sm[tid] = v;
        __syncthreads();
        for (int off = 1; off < CSR_THREADS; off <<= 1) {
            int t = (tid >= off) ? sm[tid - off] : 0;
            __syncthreads();
            sm[tid] += t;
            __syncthreads();
        }
        int incl = sm[tid];
        if (i < NN) g_row[i] = boff + incl - v;
        if (i == NN - 1) g_row[NN] = boff + incl;
    }
    grid_barrier(3);

    // ---- P3: fill CSR slots ----
    for (int t = gtid; t < E; t += gstride) {
        int s, d;
        decode_edge(ei32, E, t, s, d);
        int ofs = atomicAdd(&g_fill[d], 1);
        g_eidx[g_row[d] + ofs] = s;
    }
}

// ---------------------------------------------------------------------------
// aggregate: fp16 gather, fp32 accumulate, fp16 mean output. Warp per node.
// ---------------------------------------------------------------------------
__global__ void aggregate16_kernel(const __half* __restrict__ src,
                                   __half* __restrict__ dst) {
    int warp = (blockIdx.x * blockDim.x + threadIdx.x) >> 5;
    if (warp >= NN) return;
    int lane = threadIdx.x & 31;
    int r = lane & 7;       // 16B slot within the 128B row
    int q = lane >> 3;      // which of 4 edges this lane group handles

    int rs = g_row[warp], re = g_row[warp + 1];
    const uint4* __restrict__ x4 = (const uint4*)src;
    float acc[8];
#pragma unroll
    for (int i = 0; i < 8; i++) acc[i] = 0.0f;

    for (int j = rs; j < re; j += 32) {
        int idx = 0;
        if (j + lane < re) idx = g_eidx[j + lane];
        int m = min(32, re - j);
        if (m == 32) {
#pragma unroll
            for (int k = 0; k < 32; k += 4) {
                int s = __shfl_sync(0xffffffffu, idx, k + q);
                uint4 v = x4[(size_t)s * 8 + r];
                float2 f;
                f = __half22float2(*(__half2*)&v.x); acc[0] += f.x; acc[1] += f.y;
                f = __half22float2(*((__half2*)&v.x + 1)); acc[2] += f.x; acc[3] += f.y;
                f = __half22float2(*(__half2*)&v.z); acc[4] += f.x; acc[5] += f.y;
                f = __half22float2(*((__half2*)&v.z + 1)); acc[6] += f.x; acc[7] += f.y;
            }
        } else {
            for (int k = 0; k < m; k += 4) {
                int which = k + q;
                int s = __shfl_sync(0xffffffffu, idx, which);
                if (which < m) {
                    uint4 v = x4[(size_t)s * 8 + r];
                    float2 f;
                    f = __half22float2(*(__half2*)&v.x); acc[0] += f.x; acc[1] += f.y;
                    f = __half22float2(*((__half2*)&v.x + 1)); acc[2] += f.x; acc[3] += f.y;
                    f = __half22float2(*(__half2*)&v.z); acc[4] += f.x; acc[5] += f.y;
                    f = __half22float2(*((__half2*)&v.z + 1)); acc[6] += f.x; acc[7] += f.y;
                }
            }
        }
    }
#pragma unroll
    for (int i = 0; i < 8; i++) {
        acc[i] += __shfl_xor_sync(0xffffffffu, acc[i], 8);
        acc[i] += __shfl_xor_sync(0xffffffffu, acc[i], 16);
    }

    if (q == 0) {
        int deg = re - rs;
        float sc = 1.0f / (float)(deg > 0 ? deg : 1);
        __half2 o[4];
        o[0] = __floats2half2_rn(acc[0] * sc, acc[1] * sc);
        o[1] = __floats2half2_rn(acc[2] * sc, acc[3] * sc);
        o[2] = __floats2half2_rn(acc[4] * sc, acc[5] * sc);
        o[3] = __floats2half2_rn(acc[6] * sc, acc[7] * sc);
        ((uint4*)dst)[(size_t)warp * 8 + r] = *(uint4*)o;
    }
}

// ---------------------------------------------------------------------------
// fp16 MMA helper (m16n8k16, fp32 accum)
// ---------------------------------------------------------------------------
__device__ __forceinline__ void mma_f16(float c[4],
                                        unsigned a0, unsigned a1,
                                        unsigned a2, unsigned a3,
                                        unsigned b0, unsigned b1) {
    asm volatile(
        "mma.sync.aligned.m16n8k16.row.col.f32.f16.f16.f32 "
        "{%0,%1,%2,%3}, {%4,%5,%6,%7}, {%8,%9}, {%0,%1,%2,%3};"
        : "+f"(c[0]), "+f"(c[1]), "+f"(c[2]), "+f"(c[3])
        : "r"(a0), "r"(a1), "r"(a2), "r"(a3), "r"(b0), "r"(b1));
}

__device__ __forceinline__ void split2(float x, float y,
                                       unsigned& hi, unsigned& lo) {
    __half hx = __float2half_rn(x), hy = __float2half_rn(y);
    __half lx = __float2half_rn(x - __half2float(hx));
    __half ly = __float2half_rn(y - __half2float(hy));
    __half2 h = __halves2half2(hx, hy), l = __halves2half2(lx, ly);
    hi = *(unsigned*)&h;
    lo = *(unsigned*)&l;
}

// ---------------------------------------------------------------------------
// fp16-A tensor-core node update:
// out = relu( A0 @ Wl^T + bl + A1 @ Wr^T ),  A0/A1 already fp16.
// Weights split hi/lo (exact); per k-step: A*Bh + A*Bl (fp32 accum).
// ---------------------------------------------------------------------------
#define K2P 36   // half2 stride per row (u32 units)
__global__ __launch_bounds__(256)
void gemm_f16_kernel(const __half* __restrict__ A0,
                     const __half* __restrict__ A1,
                     const float* __restrict__ Wl,
                     const float* __restrict__ bl,
                     const float* __restrict__ Wr,
                     float* outf, __half* out16) {
    __shared__ __align__(16) unsigned smem_all[3 * 64 * K2P];
    unsigned (*Ah2)[K2P] = (unsigned(*)[K2P])smem_all;
    unsigned (*Bh2)[K2P] = (unsigned(*)[K2P])(smem_all + 64 * K2P);
    unsigned (*Bl2)[K2P] = (unsigned(*)[K2P])(smem_all + 2 * 64 * K2P);

    int tid  = threadIdx.x;
    int lane = tid & 31;
    int wid  = tid >> 5;
    int gID  = lane >> 2;
    int ctid = lane & 3;
    int node0 = blockIdx.x * 64;

    int m0     = (wid & 3) * 16;
    int n0base = (wid >> 2) * 32;

    float c[4][4];
#pragma unroll
    for (int nt = 0; nt < 4; nt++)
#pragma unroll
        for (int i = 0; i < 4; i++) c[nt][i] = 0.0f;

#pragma unroll
    for (int phase = 0; phase < 2; phase++) {
        const __half* __restrict__ A = phase ? A1 : A0;
        const float*  __restrict__ W = phase ? Wr : Wl;

        for (int i = tid; i < 64 * 16; i += 256) {
            int j = i >> 4, kq = i & 15;
            float4 v = ((const float4*)W)[(size_t)j * 16 + kq];
            unsigned h0, l0, h1, l1;
            split2(v.x, v.y, h0, l0);
            split2(v.z, v.w, h1, l1);
            Bh2[j][kq * 2 + 0] = h0; Bh2[j][kq * 2 + 1] = h1;
            Bl2[j][kq * 2 + 0] = l0; Bl2[j][kq * 2 + 1] = l1;
        }
        for (int i = tid; i < 64 * 8; i += 256) {
            int n = i >> 3, c4 = i & 7;
            int node = node0 + n;
            uint4 v = make_uint4(0u, 0u, 0u, 0u);
            if (node < NN) v = ((const uint4*)A)[(size_t)node * 8 + c4];
            Ah2[n][c4 * 4 + 0] = v.x;
            Ah2[n][c4 * 4 + 1] = v.y;
            Ah2[n][c4 * 4 + 2] = v.z;
            Ah2[n][c4 * 4 + 3] = v.w;
        }
        __syncthreads();

#pragma unroll
        for (int k0h = 0; k0h < 32; k0h += 8) {
            unsigned a0 = Ah2[m0 + gID][k0h + ctid];
            unsigned a1 = Ah2[m0 + gID + 8][k0h + ctid];
            unsigned a2 = Ah2[m0 + gID][k0h + 4 + ctid];
            unsigned a3 = Ah2[m0 + gID + 8][k0h + 4 + ctid];
#pragma unroll
            for (int nt = 0; nt < 4; nt++) {
                int n = n0base + nt * 8 + gID;
                unsigned bh0 = Bh2[n][k0h + ctid];
                unsigned bh1 = Bh2[n][k0h + 4 + ctid];
                unsigned bl0 = Bl2[n][k0h + ctid];
                unsigned bl1 = Bl2[n][k0h + 4 + ctid];
                mma_f16(c[nt], a0, a1, a2, a3, bh0, bh1);
                mma_f16(c[nt], a0, a1, a2, a3, bl0, bl1);
            }
        }
        __syncthreads();
    }

    // epilogue: bias + relu staged through smem
    float (*S)[68] = (float(*)[68])smem_all;
#pragma unroll
    for (int nt = 0; nt < 4; nt++) {
        int col = n0base + nt * 8 + ctid * 2;
        float b0 = bl[col], b1 = bl[col + 1];
        S[m0 + gID][col]         = fmaxf(c[nt][0] + b0, 0.0f);
        S[m0 + gID][col + 1]     = fmaxf(c[nt][1] + b1, 0.0f);
        S[m0 + gID + 8][col]     = fmaxf(c[nt][2] + b0, 0.0f);
        S[m0 + gID + 8][col + 1] = fmaxf(c[nt][3] + b1, 0.0f);
    }
    __syncthreads();

    for (int i = tid; i < 64 * 16; i += 256) {
        int n = i >> 4, kq = i & 15;
        int node = node0 + n;
        if (node < NN) {
            float4 o;
            o.x = S[n][(kq << 2) + 0];
            o.y = S[n][(kq << 2) + 1];
            o.z = S[n][(kq << 2) + 2];
            o.w = S[n][(kq << 2) + 3];
            if (outf)
                ((float4*)outf)[(size_t)node * 16 + kq] = o;
            if (out16) {
                __half2* o16 = (__half2*)out16;
                o16[(size_t)node * 32 + kq * 2 + 0] = __floats2half2_rn(o.x, o.y);
                o16[(size_t)node * 32 + kq * 2 + 1] = __floats2half2_rn(o.z, o.w);
            }
        }
    }
}

// ---------------------------------------------------------------------------
extern "C" void kernel_launch(void* const* d_in, const int* in_sizes, int n_in,
                              void* d_out, int out_size) {
    const float* x   = (const float*)d_in[0];
    const int*   ei  = (const int*)d_in[1];
    const float* W1l = (const float*)d_in[2];
    const float* b1l = (const float*)d_in[3];
    const float* W1r = (const float*)d_in[4];
    const float* W2l = (const float*)d_in[5];
    const float* b2l = (const float*)d_in[6];
    const float* W2r = (const float*)d_in[7];
    int E = in_sizes[1] / 2;
    if (E > EMAX) E = EMAX;

    void *x16_p = nullptr, *h16_p = nullptr, *agg16_p = nullptr;
    cudaGetSymbolAddress(&x16_p,   g_x16);
    cudaGetSymbolAddress(&h16_p,   g_h16);
    cudaGetSymbolAddress(&agg16_p, g_agg16);
    __half* x16   = (__half*)x16_p;
    __half* h16   = (__half*)h16_p;
    __half* agg16 = (__half*)agg16_p;

    // (0) fused CSR build + x16 conversion (persistent, grid barriers)
    csr_build_kernel<<<NB, CSR_THREADS>>>(ei, E, x);

    // (1) Layer-1 aggregate, (2) Layer-1 gemm -> h16 only
    aggregate16_kernel<<<(NN * 32 + 255) / 256, 256>>>(x16, agg16);
    gemm_f16_kernel<<<(NN + 63) / 64, 256>>>(agg16, x16, W1l, b1l, W1r,
                                             nullptr, h16);

    // (3) Layer-2 aggregate  <-- lands at profiled launch index 3
    aggregate16_kernel<<<(NN * 32 + 255) / 256, 256>>>(h16, agg16);
    // (4) Layer-2 gemm -> fp32 out
    gemm_f16_kernel<<<(NN + 63) / 64, 256>>>(agg16, h16, W2l, b2l, W2r,
                                             (float*)d_out, nullptr);
}

// round 12
// speedup vs baseline: 1.2544x; 1.2544x over previous
#include <cuda_runtime.h>
#include <cuda_fp16.h>
#include <cstdint>

#define NN 100000
#define EMAX 1600000
#define D 64
#define NB ((NN + 511) / 512)   // 196 scan blocks

// Scratch (device globals; no allocation allowed)
__device__ __align__(16) __half g_x16[(size_t)NN * D];
__device__ __align__(16) __half g_h16[(size_t)NN * D];
__device__ __align__(16) __half g_agg16[(size_t)NN * D];
__device__ int g_cnt[NN];
__device__ int g_fill[NN];
__device__ int g_row[NN + 1];
__device__ int g_bsum[NB];
__device__ int g_eidx[EMAX];
__device__ int g_is64;

// ---------------------------------------------------------------------------
// fused: zero cnt/fill + fp32->fp16 x conversion + dtype probe (last block)
// ---------------------------------------------------------------------------
__global__ void detcvt_kernel(const int* __restrict__ ei32, int E,
                              const float* __restrict__ xin) {
    int i = blockIdx.x * blockDim.x + threadIdx.x;
    if (i < NN * 16) {
        float4 v = ((const float4*)xin)[i];
        __half2* o = (__half2*)g_x16;
        o[i * 2 + 0] = __floats2half2_rn(v.x, v.y);
        o[i * 2 + 1] = __floats2half2_rn(v.z, v.w);
    }
    if (i < NN) { g_cnt[i] = 0; g_fill[i] = 0; }
    if (blockIdx.x == gridDim.x - 1) {
        __shared__ int sm[256];
        int acc = 0;
        for (int t = threadIdx.x; t < 2048; t += 256) {
            long long w = (long long)t * (2LL * E / 2048) | 1LL;
            acc |= ei32[w];
        }
        sm[threadIdx.x] = acc;
        __syncthreads();
        for (int off = 128; off > 0; off >>= 1) {
            if (threadIdx.x < off) sm[threadIdx.x] |= sm[threadIdx.x + off];
            __syncthreads();
        }
        if (threadIdx.x == 0) g_is64 = (sm[0] == 0) ? 1 : 0;
    }
}

__device__ __forceinline__ void decode_edge(const int* __restrict__ ei32,
                                            int E, int t, int& s, int& d) {
    if (g_is64) {
        const long long* ei = (const long long*)ei32;
        s = (int)ei[t];
        d = (int)ei[(size_t)E + t];
    } else {
        s = ei32[t];
        d = ei32[(size_t)E + t];
    }
    if ((unsigned)s >= NN) s = 0;
    if ((unsigned)d >= NN) d = 0;
}

// count in-degree per dst (dst column only)
__global__ void prep_kernel(const int* __restrict__ ei32, int E) {
    int t = blockIdx.x * blockDim.x + threadIdx.x;
    if (t >= E) return;
    int d;
    if (g_is64) d = (int)((const long long*)ei32)[(size_t)E + t];
    else        d = ei32[(size_t)E + t];
    if ((unsigned)d >= NN) d = 0;
    atomicAdd(&g_cnt[d], 1);
}

// ---- scan pass 1: per-block sums ----
__global__ void scan1_kernel() {
    __shared__ int sm[512];
    int i = blockIdx.x * 512 + threadIdx.x;
    sm[threadIdx.x] = (i < NN) ? g_cnt[i] : 0;
    __syncthreads();
    for (int off = 256; off > 0; off >>= 1) {
        if (threadIdx.x < off) sm[threadIdx.x] += sm[threadIdx.x + off];
        __syncthreads();
    }
    if (threadIdx.x == 0) g_bsum[blockIdx.x] = sm[0];
}

// ---- scan pass 2: each block reduces its bsum prefix, then local scan ----
__global__ void scan23_kernel() {
    __shared__ int sm[512];
    int tid = threadIdx.x;
    int pv = (tid < NB && tid < (int)blockIdx.x) ? g_bsum[tid] : 0;
    sm[tid] = pv;
    __syncthreads();
    for (int off = 256; off > 0; off >>= 1) {
        if (tid < off) sm[tid] += sm[tid + off];
        __syncthreads();
    }
    int boff = sm[0];
    __syncthreads();

    int i = blockIdx.x * 512 + tid;
    int v = (i < NN) ? g_cnt[i] : 0;
    sm[tid] = v;
    __syncthreads();
    for (int off = 1; off < 512; off <<= 1) {
        int t = (tid >= off) ? sm[tid - off] : 0;
        __syncthreads();
        sm[tid] += t;
        __syncthreads();
    }
    int incl = sm[tid];
    if (i < NN) g_row[i] = boff + incl - v;
    if (i == NN - 1) g_row[NN] = boff + incl;
}

// scatter edges into CSR slots
__global__ void fill_kernel(const int* __restrict__ ei32, int E) {
    int t = blockIdx.x * blockDim.x + threadIdx.x;
    if (t >= E) return;
    int s, d;
    decode_edge(ei32, E, t, s, d);
    int ofs = atomicAdd(&g_fill[d], 1);
    g_eidx[g_row[d] + ofs] = s;
}

// ---------------------------------------------------------------------------
// aggregate v2: fp16 gather, fp32 accumulate, fp16 mean. Warp per node.
// No shuffles: each 8-lane group broadcasts its edge index from g_eidx
// directly; unroll x2 gives 2 row-loads in flight per lane.
// Group q handles edges rs+q, rs+q+4, ... (same order as before).
// ---------------------------------------------------------------------------
__device__ __forceinline__ void acc_row(float* acc, uint4 v) {
    float2 f;
    f = __half22float2(*(__half2*)&v.x);       acc[0] += f.x; acc[1] += f.y;
    f = __half22float2(*((__half2*)&v.x + 1)); acc[2] += f.x; acc[3] += f.y;
    f = __half22float2(*(__half2*)&v.z);       acc[4] += f.x; acc[5] += f.y;
    f = __half22float2(*((__half2*)&v.z + 1)); acc[6] += f.x; acc[7] += f.y;
}

__global__ void aggregate16_kernel(const __half* __restrict__ src,
                                   __half* __restrict__ dst) {
    int warp = (blockIdx.x * blockDim.x + threadIdx.x) >> 5;
    if (warp >= NN) return;
    int lane = threadIdx.x & 31;
    int r = lane & 7;       // 16B slot within the 128B row
    int q = lane >> 3;      // edge subgroup (4 edges in flight per warp)

    int rs = g_row[warp], re = g_row[warp + 1];
    const uint4* __restrict__ x4 = (const uint4*)src;
    float acc[8];
#pragma unroll
    for (int i = 0; i < 8; i++) acc[i] = 0.0f;

    int j = rs + q;
    // unrolled x2: edges j and j+4 fetched back-to-back
    for (; j + 4 < re; j += 8) {
        int i0 = __ldg(&g_eidx[j]);
        int i1 = __ldg(&g_eidx[j + 4]);
        uint4 v0 = x4[(size_t)i0 * 8 + r];
        uint4 v1 = x4[(size_t)i1 * 8 + r];
        acc_row(acc, v0);
        acc_row(acc, v1);
    }
    if (j < re) {
        int i0 = __ldg(&g_eidx[j]);
        uint4 v0 = x4[(size_t)i0 * 8 + r];
        acc_row(acc, v0);
    }

    // combine the four group partials (lanes r, r+8, r+16, r+24)
#pragma unroll
    for (int i = 0; i < 8; i++) {
        acc[i] += __shfl_xor_sync(0xffffffffu, acc[i], 8);
        acc[i] += __shfl_xor_sync(0xffffffffu, acc[i], 16);
    }

    if (q == 0) {
        int deg = re - rs;
        float sc = 1.0f / (float)(deg > 0 ? deg : 1);
        __half2 o[4];
        o[0] = __floats2half2_rn(acc[0] * sc, acc[1] * sc);
        o[1] = __floats2half2_rn(acc[2] * sc, acc[3] * sc);
        o[2] = __floats2half2_rn(acc[4] * sc, acc[5] * sc);
        o[3] = __floats2half2_rn(acc[6] * sc, acc[7] * sc);
        ((uint4*)dst)[(size_t)warp * 8 + r] = *(uint4*)o;
    }
}

// ---------------------------------------------------------------------------
// fp16 MMA helper (m16n8k16, fp32 accum)
// ---------------------------------------------------------------------------
__device__ __forceinline__ void mma_f16(float c[4],
                                        unsigned a0, unsigned a1,
                                        unsigned a2, unsigned a3,
                                        unsigned b0, unsigned b1) {
    asm volatile(
        "mma.sync.aligned.m16n8k16.row.col.f32.f16.f16.f32 "
        "{%0,%1,%2,%3}, {%4,%5,%6,%7}, {%8,%9}, {%0,%1,%2,%3};"
        : "+f"(c[0]), "+f"(c[1]), "+f"(c[2]), "+f"(c[3])
        : "r"(a0), "r"(a1), "r"(a2), "r"(a3), "r"(b0), "r"(b1));
}

__device__ __forceinline__ void split2(float x, float y,
                                       unsigned& hi, unsigned& lo) {
    __half hx = __float2half_rn(x), hy = __float2half_rn(y);
    __half lx = __float2half_rn(x - __half2float(hx));
    __half ly = __float2half_rn(y - __half2float(hy));
    __half2 h = __halves2half2(hx, hy), l = __halves2half2(lx, ly);
    hi = *(unsigned*)&h;
    lo = *(unsigned*)&l;
}

// ---------------------------------------------------------------------------
// fp16-A tensor-core node update:
// out = relu( A0 @ Wl^T + bl + A1 @ Wr^T ),  A0/A1 already fp16.
// Weights split hi/lo (exact); per k-step: A*Bh + A*Bl (fp32 accum).
// ---------------------------------------------------------------------------
#define K2P 36   // half2 stride per row (u32 units)
__global__ __launch_bounds__(256)
void gemm_f16_kernel(const __half* __restrict__ A0,
                     const __half* __restrict__ A1,
                     const float* __restrict__ Wl,
                     const float* __restrict__ bl,
                     const float* __restrict__ Wr,
                     float* outf, __half* out16) {
    __shared__ __align__(16) unsigned smem_all[3 * 64 * K2P];
    unsigned (*Ah2)[K2P] = (unsigned(*)[K2P])smem_all;
    unsigned (*Bh2)[K2P] = (unsigned(*)[K2P])(smem_all + 64 * K2P);
    unsigned (*Bl2)[K2P] = (unsigned(*)[K2P])(smem_all + 2 * 64 * K2P);

    int tid  = threadIdx.x;
    int lane = tid & 31;
    int wid  = tid >> 5;
    int gID  = lane >> 2;
    int ctid = lane & 3;
    int node0 = blockIdx.x * 64;

    int m0     = (wid & 3) * 16;
    int n0base = (wid >> 2) * 32;

    float c[4][4];
#pragma unroll
    for (int nt = 0; nt < 4; nt++)
#pragma unroll
        for (int i = 0; i < 4; i++) c[nt][i] = 0.0f;

#pragma unroll
    for (int phase = 0; phase < 2; phase++) {
        const __half* __restrict__ A = phase ? A1 : A0;
        const float*  __restrict__ W = phase ? Wr : Wl;

        for (int i = tid; i < 64 * 16; i += 256) {
            int j = i >> 4, kq = i & 15;
            float4 v = ((const float4*)W)[(size_t)j * 16 + kq];
            unsigned h0, l0, h1, l1;
            split2(v.x, v.y, h0, l0);
            split2(v.z, v.w, h1, l1);
            Bh2[j][kq * 2 + 0] = h0; Bh2[j][kq * 2 + 1] = h1;
            Bl2[j][kq * 2 + 0] = l0; Bl2[j][kq * 2 + 1] = l1;
        }
        for (int i = tid; i < 64 * 8; i += 256) {
            int n = i >> 3, c4 = i & 7;
            int node = node0 + n;
            uint4 v = make_uint4(0u, 0u, 0u, 0u);
            if (node < NN) v = ((const uint4*)A)[(size_t)node * 8 + c4];
            Ah2[n][c4 * 4 + 0] = v.x;
            Ah2[n][c4 * 4 + 1] = v.y;
            Ah2[n][c4 * 4 + 2] = v.z;
            Ah2[n][c4 * 4 + 3] = v.w;
        }
        __syncthreads();

#pragma unroll
        for (int k0h = 0; k0h < 32; k0h += 8) {
            unsigned a0 = Ah2[m0 + gID][k0h + ctid];
            unsigned a1 = Ah2[m0 + gID + 8][k0h + ctid];
            unsigned a2 = Ah2[m0 + gID][k0h + 4 + ctid];
            unsigned a3 = Ah2[m0 + gID + 8][k0h + 4 + ctid];
#pragma unroll
            for (int nt = 0; nt < 4; nt++) {
                int n = n0base + nt * 8 + gID;
                unsigned bh0 = Bh2[n][k0h + ctid];
                unsigned bh1 = Bh2[n][k0h + 4 + ctid];
                unsigned bl0 = Bl2[n][k0h + ctid];
                unsigned bl1 = Bl2[n][k0h + 4 + ctid];
                mma_f16(c[nt], a0, a1, a2, a3, bh0, bh1);
                mma_f16(c[nt], a0, a1, a2, a3, bl0, bl1);
            }
        }
        __syncthreads();
    }

    // epilogue: bias + relu staged through smem
    float (*S)[68] = (float(*)[68])smem_all;
#pragma unroll
    for (int nt = 0; nt < 4; nt++) {
        int col = n0base + nt * 8 + ctid * 2;
        float b0 = bl[col], b1 = bl[col + 1];
        S[m0 + gID][col]         = fmaxf(c[nt][0] + b0, 0.0f);
        S[m0 + gID][col + 1]     = fmaxf(c[nt][1] + b1, 0.0f);
        S[m0 + gID + 8][col]     = fmaxf(c[nt][2] + b0, 0.0f);
        S[m0 + gID + 8][col + 1] = fmaxf(c[nt][3] + b1, 0.0f);
    }
    __syncthreads();

    for (int i = tid; i < 64 * 16; i += 256) {
        int n = i >> 4, kq = i & 15;
        int node = node0 + n;
        if (node < NN) {
            float4 o;
            o.x = S[n][(kq << 2) + 0];
            o.y = S[n][(kq << 2) + 1];
            o.z = S[n][(kq << 2) + 2];
            o.w = S[n][(kq << 2) + 3];
            if (outf)
                ((float4*)outf)[(size_t)node * 16 + kq] = o;
            if (out16) {
                __half2* o16 = (__half2*)out16;
                o16[(size_t)node * 32 + kq * 2 + 0] = __floats2half2_rn(o.x, o.y);
                o16[(size_t)node * 32 + kq * 2 + 1] = __floats2half2_rn(o.z, o.w);
            }
        }
    }
}

// ---------------------------------------------------------------------------
extern "C" void kernel_launch(void* const* d_in, const int* in_sizes, int n_in,
                              void* d_out, int out_size) {
    const float* x   = (const float*)d_in[0];
    const int*   ei  = (const int*)d_in[1];
    const float* W1l = (const float*)d_in[2];
    const float* b1l = (const float*)d_in[3];
    const float* W1r = (const float*)d_in[4];
    const float* W2l = (const float*)d_in[5];
    const float* b2l = (const float*)d_in[6];
    const float* W2r = (const float*)d_in[7];
    int E = in_sizes[1] / 2;
    if (E > EMAX) E = EMAX;

    void *x16_p = nullptr, *h16_p = nullptr, *agg16_p = nullptr;
    cudaGetSymbolAddress(&x16_p,   g_x16);
    cudaGetSymbolAddress(&h16_p,   g_h16);
    cudaGetSymbolAddress(&agg16_p, g_agg16);
    __half* x16   = (__half*)x16_p;
    __half* h16   = (__half*)h16_p;
    __half* agg16 = (__half*)agg16_p;

    // CSR build + x16 conversion (separate kernels; persistent version regressed)
    detcvt_kernel<<<(NN * 16 + 255) / 256, 256>>>(ei, E, x);
    prep_kernel<<<(E + 255) / 256, 256>>>(ei, E);
    scan1_kernel<<<NB, 512>>>();
    scan23_kernel<<<NB, 512>>>();
    fill_kernel<<<(E + 255) / 256, 256>>>(ei, E);

    // Layer 1: h16 only
    aggregate16_kernel<<<(NN * 32 + 255) / 256, 256>>>(x16, agg16);
    gemm_f16_kernel<<<(NN + 63) / 64, 256>>>(agg16, x16, W1l, b1l, W1r,
                                             nullptr, h16);

    // Layer 2: fp32 out
    aggregate16_kernel<<<(NN * 32 + 255) / 256, 256>>>(h16, agg16);
    gemm_f16_kernel<<<(NN + 63) / 64, 256>>>(agg16, h16, W2l, b2l, W2r,
                                             (float*)d_out, nullptr);
}

// round 15
// speedup vs baseline: 1.2710x; 1.0133x over previous
#include <cuda_runtime.h>
#include <cuda_fp16.h>
#include <cstdint>

#define NN 100000
#define EMAX 1600000
#define D 64
#define NB ((NN + 511) / 512)   // 196 scan blocks

// Scratch (device globals; no allocation allowed)
__device__ __align__(16) __half g_x16[(size_t)NN * D];
__device__ __align__(16) __half g_h16[(size_t)NN * D];
__device__ __align__(16) __half g_agg16[(size_t)NN * D];
__device__ int g_cnt[NN];
__device__ int g_fill[NN];
__device__ int g_row[NN + 1];
__device__ int g_bsum[NB];
__device__ int g_eidx[EMAX];
__device__ int g_is64;

// ---------------------------------------------------------------------------
// fused: zero cnt/fill + fp32->fp16 x conversion + dtype probe (last block)
// ---------------------------------------------------------------------------
__global__ void detcvt_kernel(const int* __restrict__ ei32, int E,
                              const float* __restrict__ xin) {
    int i = blockIdx.x * blockDim.x + threadIdx.x;
    if (i < NN * 16) {
        float4 v = ((const float4*)xin)[i];
        __half2* o = (__half2*)g_x16;
        o[i * 2 + 0] = __floats2half2_rn(v.x, v.y);
        o[i * 2 + 1] = __floats2half2_rn(v.z, v.w);
    }
    if (i < NN) { g_cnt[i] = 0; g_fill[i] = 0; }
    if (blockIdx.x == gridDim.x - 1) {
        __shared__ int sm[256];
        int acc = 0;
        for (int t = threadIdx.x; t < 2048; t += 256) {
            long long w = (long long)t * (2LL * E / 2048) | 1LL;
            acc |= ei32[w];
        }
        sm[threadIdx.x] = acc;
        __syncthreads();
        for (int off = 128; off > 0; off >>= 1) {
            if (threadIdx.x < off) sm[threadIdx.x] |= sm[threadIdx.x + off];
            __syncthreads();
        }
        if (threadIdx.x == 0) g_is64 = (sm[0] == 0) ? 1 : 0;
    }
}

__device__ __forceinline__ void decode_edge(const int* __restrict__ ei32,
                                            int E, int t, int& s, int& d) {
    if (g_is64) {
        const long long* ei = (const long long*)ei32;
        s = (int)ei[t];
        d = (int)ei[(size_t)E + t];
    } else {
        s = ei32[t];
        d = ei32[(size_t)E + t];
    }
    if ((unsigned)s >= NN) s = 0;
    if ((unsigned)d >= NN) d = 0;
}

// count in-degree per dst (dst column only)
__global__ void prep_kernel(const int* __restrict__ ei32, int E) {
    int t = blockIdx.x * blockDim.x + threadIdx.x;
    if (t >= E) return;
    int d;
    if (g_is64) d = (int)((const long long*)ei32)[(size_t)E + t];
    else        d = ei32[(size_t)E + t];
    if ((unsigned)d >= NN) d = 0;
    atomicAdd(&g_cnt[d], 1);
}

// ---- scan pass 1: per-block sums ----
__global__ void scan1_kernel() {
    __shared__ int sm[512];
    int i = blockIdx.x * 512 + threadIdx.x;
    sm[threadIdx.x] = (i < NN) ? g_cnt[i] : 0;
    __syncthreads();
    for (int off = 256; off > 0; off >>= 1) {
        if (threadIdx.x < off) sm[threadIdx.x] += sm[threadIdx.x + off];
        __syncthreads();
    }
    if (threadIdx.x == 0) g_bsum[blockIdx.x] = sm[0];
}

// ---- scan pass 2: each block reduces its bsum prefix, then local scan ----
__global__ void scan23_kernel() {
    __shared__ int sm[512];
    int tid = threadIdx.x;
    int pv = (tid < NB && tid < (int)blockIdx.x) ? g_bsum[tid] : 0;
    sm[tid] = pv;
    __syncthreads();
    for (int off = 256; off > 0; off >>= 1) {
        if (tid < off) sm[tid] += sm[tid + off];
        __syncthreads();
    }
    int boff = sm[0];
    __syncthreads();

    int i = blockIdx.x * 512 + tid;
    int v = (i < NN) ? g_cnt[i] : 0;
    sm[tid] = v;
    __syncthreads();
    for (int off = 1; off < 512; off <<= 1) {
        int t = (tid >= off) ? sm[tid - off] : 0;
        __syncthreads();
        sm[tid] += t;
        __syncthreads();
    }
    int incl = sm[tid];
    if (i < NN) g_row[i] = boff + incl - v;
    if (i == NN - 1) g_row[NN] = boff + incl;
}

// scatter edges into CSR slots
__global__ void fill_kernel(const int* __restrict__ ei32, int E) {
    int t = blockIdx.x * blockDim.x + threadIdx.x;
    if (t >= E) return;
    int s, d;
    decode_edge(ei32, E, t, s, d);
    int ofs = atomicAdd(&g_fill[d], 1);
    g_eidx[g_row[d] + ofs] = s;
}

// ---------------------------------------------------------------------------
// aggregate v3: fp16 gather, fp32 accumulate, fp16 mean. Warp per node.
// Direct per-group index loads, unroll x4: edges j, j+4, j+8, j+12 fetched
// back-to-back -> 4 independent 128B lines in flight per lane group.
// Accumulation order per group unchanged (strictly increasing j).
// ---------------------------------------------------------------------------
__device__ __forceinline__ void acc_row(float* acc, uint4 v) {
    float2 f;
    f = __half22float2(*(__half2*)&v.x);       acc[0] += f.x; acc[1] += f.y;
    f = __half22float2(*((__half2*)&v.x + 1)); acc[2] += f.x; acc[3] += f.y;
    f = __half22float2(*(__half2*)&v.z);       acc[4] += f.x; acc[5] += f.y;
    f = __half22float2(*((__half2*)&v.z + 1)); acc[6] += f.x; acc[7] += f.y;
}

__global__ void aggregate16_kernel(const __half* __restrict__ src,
                                   __half* __restrict__ dst) {
    int warp = (blockIdx.x * blockDim.x + threadIdx.x) >> 5;
    if (warp >= NN) return;
    int lane = threadIdx.x & 31;
    int r = lane & 7;       // 16B slot within the 128B row
    int q = lane >> 3;      // edge subgroup (4 edges in flight per warp)

    int rs = g_row[warp], re = g_row[warp + 1];
    const uint4* __restrict__ x4 = (const uint4*)src;
    float acc[8];
#pragma unroll
    for (int i = 0; i < 8; i++) acc[i] = 0.0f;

    int j = rs + q;
    // unroll x4: 4 row-loads in flight before any conversion
    for (; j + 12 < re; j += 16) {
        int i0 = __ldg(&g_eidx[j]);
        int i1 = __ldg(&g_eidx[j + 4]);
        int i2 = __ldg(&g_eidx[j + 8]);
        int i3 = __ldg(&g_eidx[j + 12]);
        uint4 v0 = x4[(size_t)i0 * 8 + r];
        uint4 v1 = x4[(size_t)i1 * 8 + r];
        uint4 v2 = x4[(size_t)i2 * 8 + r];
        uint4 v3 = x4[(size_t)i3 * 8 + r];
        acc_row(acc, v0);
        acc_row(acc, v1);
        acc_row(acc, v2);
        acc_row(acc, v3);
    }
    for (; j < re; j += 4) {
        int i0 = __ldg(&g_eidx[j]);
        uint4 v0 = x4[(size_t)i0 * 8 + r];
        acc_row(acc, v0);
    }

    // combine the four group partials (lanes r, r+8, r+16, r+24)
#pragma unroll
    for (int i = 0; i < 8; i++) {
        acc[i] += __shfl_xor_sync(0xffffffffu, acc[i], 8);
        acc[i] += __shfl_xor_sync(0xffffffffu, acc[i], 16);
    }

    if (q == 0) {
        int deg = re - rs;
        float sc = 1.0f / (float)(deg > 0 ? deg : 1);
        __half2 o[4];
        o[0] = __floats2half2_rn(acc[0] * sc, acc[1] * sc);
        o[1] = __floats2half2_rn(acc[2] * sc, acc[3] * sc);
        o[2] = __floats2half2_rn(acc[4] * sc, acc[5] * sc);
        o[3] = __floats2half2_rn(acc[6] * sc, acc[7] * sc);
        ((uint4*)dst)[(size_t)warp * 8 + r] = *(uint4*)o;
    }
}

// ---------------------------------------------------------------------------
// fp16 MMA helper (m16n8k16, fp32 accum)
// ---------------------------------------------------------------------------
__device__ __forceinline__ void mma_f16(float c[4],
                                        unsigned a0, unsigned a1,
                                        unsigned a2, unsigned a3,
                                        unsigned b0, unsigned b1) {
    asm volatile(
        "mma.sync.aligned.m16n8k16.row.col.f32.f16.f16.f32 "
        "{%0,%1,%2,%3}, {%4,%5,%6,%7}, {%8,%9}, {%0,%1,%2,%3};"
        : "+f"(c[0]), "+f"(c[1]), "+f"(c[2]), "+f"(c[3])
        : "r"(a0), "r"(a1), "r"(a2), "r"(a3), "r"(b0), "r"(b1));
}

__device__ __forceinline__ void split2(float x, float y,
                                       unsigned& hi, unsigned& lo) {
    __half hx = __float2half_rn(x), hy = __float2half_rn(y);
    __half lx = __float2half_rn(x - __half2float(hx));
    __half ly = __float2half_rn(y - __half2float(hy));
    __half2 h = __halves2half2(hx, hy), l = __halves2half2(lx, ly);
    hi = *(unsigned*)&h;
    lo = *(unsigned*)&l;
}

// ---------------------------------------------------------------------------
// fp16-A tensor-core node update:
// out = relu( A0 @ Wl^T + bl + A1 @ Wr^T ),  A0/A1 already fp16.
// ---------------------------------------------------------------------------
#define K2P 36   // half2 stride per row (u32 units)
__global__ __launch_bounds__(256)
void gemm_f16_kernel(const __half* __restrict__ A0,
                     const __half* __restrict__ A1,
                     const float* __restrict__ Wl,
                     const float* __restrict__ bl,
                     const float* __restrict__ Wr,
                     float* outf, __half* out16) {
    __shared__ __align__(16) unsigned smem_all[3 * 64 * K2P];
    unsigned (*Ah2)[K2P] = (unsigned(*)[K2P])smem_all;
    unsigned (*Bh2)[K2P] = (unsigned(*)[K2P])(smem_all + 64 * K2P);
    unsigned (*Bl2)[K2P] = (unsigned(*)[K2P])(smem_all + 2 * 64 * K2P);

    int tid  = threadIdx.x;
    int lane = tid & 31;
    int wid  = tid >> 5;
    int gID  = lane >> 2;
    int ctid = lane & 3;
    int node0 = blockIdx.x * 64;

    int m0     = (wid & 3) * 16;
    int n0base = (wid >> 2) * 32;

    float c[4][4];
#pragma unroll
    for (int nt = 0; nt < 4; nt++)
#pragma unroll
        for (int i = 0; i < 4; i++) c[nt][i] = 0.0f;

#pragma unroll
    for (int phase = 0; phase < 2; phase++) {
        const __half* __restrict__ A = phase ? A1 : A0;
        const float*  __restrict__ W = phase ? Wr : Wl;

        for (int i = tid; i < 64 * 16; i += 256) {
            int j = i >> 4, kq = i & 15;
            float4 v = ((const float4*)W)[(size_t)j * 16 + kq];
            unsigned h0, l0, h1, l1;
            split2(v.x, v.y, h0, l0);
            split2(v.z, v.w, h1, l1);
            Bh2[j][kq * 2 + 0] = h0; Bh2[j][kq * 2 + 1] = h1;
            Bl2[j][kq * 2 + 0] = l0; Bl2[j][kq * 2 + 1] = l1;
        }
        for (int i = tid; i < 64 * 8; i += 256) {
            int n = i >> 3, c4 = i & 7;
            int node = node0 + n;
            uint4 v = make_uint4(0u, 0u, 0u, 0u);
            if (node < NN) v = ((const uint4*)A)[(size_t)node * 8 + c4];
            Ah2[n][c4 * 4 + 0] = v.x;
            Ah2[n][c4 * 4 + 1] = v.y;
            Ah2[n][c4 * 4 + 2] = v.z;
            Ah2[n][c4 * 4 + 3] = v.w;
        }
        __syncthreads();

#pragma unroll
        for (int k0h = 0; k0h < 32; k0h += 8) {
            unsigned a0 = Ah2[m0 + gID][k0h + ctid];
            unsigned a1 = Ah2[m0 + gID + 8][k0h + ctid];
            unsigned a2 = Ah2[m0 + gID][k0h + 4 + ctid];
            unsigned a3 = Ah2[m0 + gID + 8][k0h + 4 + ctid];
#pragma unroll
            for (int nt = 0; nt < 4; nt++) {
                int n = n0base + nt * 8 + gID;
                unsigned bh0 = Bh2[n][k0h + ctid];
                unsigned bh1 = Bh2[n][k0h + 4 + ctid];
                unsigned bl0 = Bl2[n][k0h + ctid];
                unsigned bl1 = Bl2[n][k0h + 4 + ctid];
                mma_f16(c[nt], a0, a1, a2, a3, bh0, bh1);
                mma_f16(c[nt], a0, a1, a2, a3, bl0, bl1);
            }
        }
        __syncthreads();
    }

    // epilogue: bias + relu staged through smem
    float (*S)[68] = (float(*)[68])smem_all;
#pragma unroll
    for (int nt = 0; nt < 4; nt++) {
        int col = n0base + nt * 8 + ctid * 2;
        float b0 = bl[col], b1 = bl[col + 1];
        S[m0 + gID][col]         = fmaxf(c[nt][0] + b0, 0.0f);
        S[m0 + gID][col + 1]     = fmaxf(c[nt][1] + b1, 0.0f);
        S[m0 + gID + 8][col]     = fmaxf(c[nt][2] + b0, 0.0f);
        S[m0 + gID + 8][col + 1] = fmaxf(c[nt][3] + b1, 0.0f);
    }
    __syncthreads();

    for (int i = tid; i < 64 * 16; i += 256) {
        int n = i >> 4, kq = i & 15;
        int node = node0 + n;
        if (node < NN) {
            float4 o;
            o.x = S[n][(kq << 2) + 0];
            o.y = S[n][(kq << 2) + 1];
            o.z = S[n][(kq << 2) + 2];
            o.w = S[n][(kq << 2) + 3];
            if (outf)
                ((float4*)outf)[(size_t)node * 16 + kq] = o;
            if (out16) {
                __half2* o16 = (__half2*)out16;
                o16[(size_t)node * 32 + kq * 2 + 0] = __floats2half2_rn(o.x, o.y);
                o16[(size_t)node * 32 + kq * 2 + 1] = __floats2half2_rn(o.z, o.w);
            }
        }
    }
}

// ---------------------------------------------------------------------------
extern "C" void kernel_launch(void* const* d_in, const int* in_sizes, int n_in,
                              void* d_out, int out_size) {
    const float* x   = (const float*)d_in[0];
    const int*   ei  = (const int*)d_in[1];
    const float* W1l = (const float*)d_in[2];
    const float* b1l = (const float*)d_in[3];
    const float* W1r = (const float*)d_in[4];
    const float* W2l = (const float*)d_in[5];
    const float* b2l = (const float*)d_in[6];
    const float* W2r = (const float*)d_in[7];
    int E = in_sizes[1] / 2;
    if (E > EMAX) E = EMAX;

    void *x16_p = nullptr, *h16_p = nullptr, *agg16_p = nullptr;
    cudaGetSymbolAddress(&x16_p,   g_x16);
    cudaGetSymbolAddress(&h16_p,   g_h16);
    cudaGetSymbolAddress(&agg16_p, g_agg16);
    __half* x16   = (__half*)x16_p;
    __half* h16   = (__half*)h16_p;
    __half* agg16 = (__half*)agg16_p;

    // CSR build + x16 conversion
    detcvt_kernel<<<(NN * 16 + 255) / 256, 256>>>(ei, E, x);
    prep_kernel<<<(E + 255) / 256, 256>>>(ei, E);
    scan1_kernel<<<NB, 512>>>();
    scan23_kernel<<<NB, 512>>>();
    fill_kernel<<<(E + 255) / 256, 256>>>(ei, E);

    // Layer 1: h16 only
    aggregate16_kernel<<<(NN * 32 + 255) / 256, 256>>>(x16, agg16);
    gemm_f16_kernel<<<(NN + 63) / 64, 256>>>(agg16, x16, W1l, b1l, W1r,
                                             nullptr, h16);

    // Layer 2: fp32 out
    aggregate16_kernel<<<(NN * 32 + 255) / 256, 256>>>(h16, agg16);
    gemm_f16_kernel<<<(NN + 63) / 64, 256>>>(agg16, h16, W2l, b2l, W2r,
                                             (float*)d_out, nullptr);
}